// round 14
// baseline (speedup 1.0000x reference)
#include <cuda_runtime.h>
#include <stdint.h>
#include <math.h>

#define BB   16384
#define HH   256
#define OUTF 256
#define LL   7
#define G4   1024
#define KT   512

// All GEMM operands stored k-interleaved: within each 8-float k-group the order is
// [k0,k4,k1,k5,k2,k6,k3,k7] so the tf32 fragment pairs (k, k+4) are adjacent 8B.
__device__ __align__(256) float g_w[(size_t)(LL + 1) * G4 * KT];   // tf32-rounded, gate-reordered, [Wih|Whh] K-concat, k-ilv
__device__ __align__(256) float g_wout[OUTF * HH];                 // tf32-rounded, k-ilv
__device__ __align__(256) float g_bias[(LL + 1) * G4];             // combined (bi+bh), gate-reordered
__device__ __align__(256) float g_x_tf[(size_t)BB * HH];           // tf32-rounded x, k-ilv
__device__ __align__(256) float g_hall_tf[(size_t)(LL + 1) * BB * HH]; // tf32-rounded h_all, k-ilv
__device__ __align__(256) float g_h_tf[(size_t)BB * HH];           // tf32-rounded h (epilogue-written), k-ilv

// ---------------- PTX helpers (arch-portable, sm_80+ baseline) ----------------
__device__ __forceinline__ uint32_t smem_u32(const void* p) {
    uint32_t a;
    asm("{ .reg .u64 t; cvta.to.shared.u64 t, %1; cvt.u32.u64 %0, t; }" : "=r"(a) : "l"(p));
    return a;
}
__device__ __forceinline__ void cp16(uint32_t s, const void* g) {
    asm volatile("cp.async.cg.shared.global [%0], [%1], 16;" :: "r"(s), "l"(g));
}
__device__ __forceinline__ void lds_v2(uint32_t addr, uint32_t& x, uint32_t& y) {
    asm volatile("ld.shared.v2.b32 {%0,%1}, [%2];" : "=r"(x), "=r"(y) : "r"(addr));
}
__device__ __forceinline__ void mma1688(float c[4], uint32_t a0, uint32_t a1,
                                        uint32_t a2, uint32_t a3,
                                        uint32_t b0, uint32_t b1) {
    asm volatile("mma.sync.aligned.m16n8k8.row.col.f32.tf32.tf32.f32 "
        "{%0,%1,%2,%3}, {%4,%5,%6,%7}, {%8,%9}, {%0,%1,%2,%3};"
        : "+f"(c[0]), "+f"(c[1]), "+f"(c[2]), "+f"(c[3])
        : "r"(a0), "r"(a1), "r"(a2), "r"(a3), "r"(b0), "r"(b1));
}
__device__ __forceinline__ float rna_tf32(float x) {
    uint32_t u; asm("cvt.rna.tf32.f32 %0, %1;" : "=r"(u) : "f"(x));
    return __uint_as_float(u);
}
__device__ __forceinline__ float sigf(float x) {
    return __fdividef(1.0f, 1.0f + __expf(-x));
}
__device__ __forceinline__ float tanhfast(float x) {
    return __fdividef(2.0f, 1.0f + __expf(-2.0f * x)) - 1.0f;
}

// ---------------- tf32 TN GEMM via mma.sync, 3-stage cp.async, fused LSTM epilogue ----------------
#define TM 128
#define TN 128
#define NTHREADS 256
#define ROWB 144                           // 128B data + 16B pad
#define STAGE_A (TM * ROWB)                // 18 KB
#define STAGE_B (TN * ROWB)                // 18 KB
#define STAGE   (STAGE_A + STAGE_B)        // 36 KB
#define NSTAGE  3
#define SMEMSZ  (NSTAGE * STAGE)           // 108 KB -> 2 CTAs/SM

template<bool FUSED>
__global__ void __launch_bounds__(NTHREADS, 2) mma_gemm(
    const float* __restrict__ A1, const float* __restrict__ A2,
    const float* __restrict__ B, int sB, int Ktot,
    const float* __restrict__ bias,
    float* __restrict__ C, int sC,
    const float* __restrict__ c_in, float* __restrict__ h_out, float* __restrict__ c_out,
    float* __restrict__ htf_out)
{
    extern __shared__ __align__(128) char dsm[];
    const int tid  = threadIdx.x;
    const int lane = tid & 31;
    const int wid  = tid >> 5;
    const int wm   = wid & 1;        // 2 warps along M (64 rows)
    const int wn   = wid >> 1;       // 4 warps along N (32 cols)
    const int m0   = blockIdx.y * TM;
    const int n0   = blockIdx.x * TN;
    const uint32_t sbase = smem_u32(dsm);

    const int niter = Ktot >> 5;     // BK = 32

    float c[4][4][4];
    #pragma unroll
    for (int i = 0; i < 4; ++i)
        #pragma unroll
        for (int j = 0; j < 4; ++j)
            #pragma unroll
            for (int q = 0; q < 4; ++q) c[i][j][q] = 0.0f;

    auto load_stage = [&](int buf, int it) {
        const int kc = it << 5;
        const uint32_t sa = sbase + buf * STAGE;
        const uint32_t sb = sa + STAGE_A;
        const float* Asrc; int koff;
        if (kc < 256) { Asrc = A1; koff = kc; } else { Asrc = A2; koff = kc - 256; }
        #pragma unroll
        for (int i = 0; i < 4; ++i) {                    // A: 128 rows x 8 chunks of 16B
            int idx = tid + i * NTHREADS;
            int row = idx >> 3, kg = idx & 7;
            cp16(sa + row * ROWB + (kg << 4),
                 Asrc + (size_t)(m0 + row) * 256 + koff + kg * 4);
        }
        #pragma unroll
        for (int i = 0; i < 4; ++i) {                    // B: 128 rows x 8 chunks
            int idx = tid + i * NTHREADS;
            int row = idx >> 3, kg = idx & 7;
            cp16(sb + row * ROWB + (kg << 4),
                 B + (size_t)(n0 + row) * sB + kc + kg * 4);
        }
        asm volatile("cp.async.commit_group;");
    };

    load_stage(0, 0);
    load_stage(1, 1);

    const int lr = lane >> 2;   // 0..7
    const int lc = lane & 3;    // k-low

    int buf = 0;
    #pragma unroll 1
    for (int i = 0; i < niter; ++i) {
        if (i + 2 < niter) {
            load_stage((buf + 2) % NSTAGE, i + 2);
            asm volatile("cp.async.wait_group 2;");
        } else {
            asm volatile("cp.async.wait_group 0;");
        }
        __syncthreads();

        const uint32_t sa = sbase + buf * STAGE;
        const uint32_t sb = sa + STAGE_A;
        // interleaved layout: fragment pair (k, k+4) lives at byte lc*8 within each
        // 32B k8-group; group ks at byte offset ks*32
        const uint32_t abase = sa + (wm * 64 + lr) * ROWB + lc * 8;
        const uint32_t bbase = sb + (wn * 32 + lr) * ROWB + lc * 8;

        #pragma unroll
        for (int ks = 0; ks < 4; ++ks) {                 // 4 k8 steps per BK=32
            const int o = ks * 32;
            uint32_t a[4][4];
            #pragma unroll
            for (int mi = 0; mi < 4; ++mi) {
                const uint32_t ab = abase + mi * (16 * ROWB);
                lds_v2(ab + o,            a[mi][0], a[mi][2]);   // (r0,k),(r0,k+4)
                lds_v2(ab + 8 * ROWB + o, a[mi][1], a[mi][3]);   // (r1,k),(r1,k+4)
            }
            uint32_t b[4][2];
            #pragma unroll
            for (int nj = 0; nj < 4; ++nj)
                lds_v2(bbase + nj * (8 * ROWB) + o, b[nj][0], b[nj][1]);
            #pragma unroll
            for (int mi = 0; mi < 4; ++mi)
                #pragma unroll
                for (int nj = 0; nj < 4; ++nj)
                    mma1688(c[mi][nj], a[mi][0], a[mi][1], a[mi][2], a[mi][3],
                            b[nj][0], b[nj][1]);
        }
        __syncthreads();
        buf = (buf + 1 == NSTAGE) ? 0 : buf + 1;
    }

    if (!FUSED) {
        #pragma unroll
        for (int mi = 0; mi < 4; ++mi) {
            const int r0 = m0 + wm * 64 + mi * 16 + lr;
            #pragma unroll
            for (int nj = 0; nj < 4; ++nj) {
                const int col = n0 + wn * 32 + nj * 8 + lc * 2;
                float bx = 0.0f, by = 0.0f;
                if (bias) { bx = bias[col]; by = bias[col + 1]; }
                *(float2*)&C[(size_t)r0 * sC + col] =
                    make_float2(c[mi][nj][0] + bx, c[mi][nj][1] + by);
                *(float2*)&C[(size_t)(r0 + 8) * sC + col] =
                    make_float2(c[mi][nj][2] + bx, c[mi][nj][3] + by);
            }
        }
    } else {
        // fused LSTM epilogue (gate-reordered cols: thread's 4 nj = gates i,f,g,o of
        // units ub, ub+1)
        const int ub = ((n0 + wn * 32) >> 2) + (lc << 1);
        // k-interleaved position of ub within its 8-group (ub even; pair at p0, p0+2)
        const int grp = ub & ~7;
        const int u3  = ub & 7;
        const int p0  = (u3 & 4) ? ((u3 & 3) * 2 + 1) : ((u3 & 3) * 2);
        float bsv[4][2];
        #pragma unroll
        for (int g = 0; g < 4; ++g) {
            bsv[g][0] = bias[n0 + wn * 32 + g * 8 + lc * 2];
            bsv[g][1] = bias[n0 + wn * 32 + g * 8 + lc * 2 + 1];
        }
        #pragma unroll
        for (int mi = 0; mi < 4; ++mi) {
            #pragma unroll
            for (int rh = 0; rh < 2; ++rh) {
                const int row = m0 + wm * 64 + mi * 16 + rh * 8 + lr;
                const float2 cin = *(const float2*)&c_in[(size_t)row * HH + ub];
                float hv[2], cv[2];
                #pragma unroll
                for (int e = 0; e < 2; ++e) {
                    const int q = rh * 2 + e;
                    float gi = sigf    (c[mi][0][q] + bsv[0][e]);
                    float gf = sigf    (c[mi][1][q] + bsv[1][e]);
                    float gg = tanhfast(c[mi][2][q] + bsv[2][e]);
                    float go = sigf    (c[mi][3][q] + bsv[3][e]);
                    float ci = e ? cin.y : cin.x;
                    cv[e] = gf * ci + gi * gg;
                    hv[e] = go * tanhfast(cv[e]);
                }
                *(float2*)&c_out[(size_t)row * HH + ub] = make_float2(cv[0], cv[1]);
                *(float2*)&h_out[(size_t)row * HH + ub] = make_float2(hv[0], hv[1]);
                float* hr = htf_out + (size_t)row * HH + grp;
                hr[p0]     = rna_tf32(hv[0]);
                hr[p0 + 2] = rna_tf32(hv[1]);
            }
        }
    }
}

// ---------------- repack / rounding kernels (once per call) ----------------
// interleave 8 floats: out = [v0.x, v1.x, v0.y, v1.y] ++ [v0.z, v1.z, v0.w, v1.w]
__device__ __forceinline__ void ilv_store8(float4 v0, float4 v1, float* dst) {
    float4 o0 = make_float4(rna_tf32(v0.x), rna_tf32(v1.x), rna_tf32(v0.y), rna_tf32(v1.y));
    float4 o1 = make_float4(rna_tf32(v0.z), rna_tf32(v1.z), rna_tf32(v0.w), rna_tf32(v1.w));
    *(float4*)(dst)     = o0;
    *(float4*)(dst + 4) = o1;
}

__global__ void __launch_bounds__(256) conv_w(
    const float* __restrict__ Wih0, const float* __restrict__ Whh0,
    const float* __restrict__ Wih,  const float* __restrict__ Whh)
{
    int t  = blockIdx.x * blockDim.x + threadIdx.x;     // 8*1024*512/8 = 524288
    int k8 = (t & 63) << 3;
    int nn = (t >> 6) & 1023;
    int l  = t >> 16;
    int gate = (nn >> 3) & 3;
    int unit = ((nn >> 5) << 3) + (nn & 7);
    int no   = gate * 256 + unit;
    const float* src;
    if (l == 0) src = (k8 < 256) ? (Wih0 + (size_t)no * 256 + k8)
                                 : (Whh0 + (size_t)no * 256 + (k8 - 256));
    else        src = (k8 < 256) ? (Wih + ((size_t)(l - 1) * G4 + no) * 256 + k8)
                                 : (Whh + ((size_t)(l - 1) * G4 + no) * 256 + (k8 - 256));
    float4 v0 = *(const float4*)src;
    float4 v1 = *(const float4*)(src + 4);
    ilv_store8(v0, v1, &g_w[((size_t)l * G4 + nn) * KT + k8]);
}

__global__ void __launch_bounds__(256) conv_wout(const float* __restrict__ Wout) {
    int t = blockIdx.x * blockDim.x + threadIdx.x;      // 256*256/8 = 8192
    int n = t >> 5, k8 = (t & 31) << 3;
    const float* src = Wout + (size_t)n * HH + k8;
    float4 v0 = *(const float4*)src;
    float4 v1 = *(const float4*)(src + 4);
    ilv_store8(v0, v1, &g_wout[(size_t)n * HH + k8]);
}

__global__ void __launch_bounds__(256) conv_bias(
    const float* __restrict__ bih0, const float* __restrict__ bhh0,
    const float* __restrict__ bih,  const float* __restrict__ bhh)
{
    int t  = blockIdx.x * blockDim.x + threadIdx.x;     // 8192
    int nn = t & 1023;
    int l  = t >> 10;
    int gate = (nn >> 3) & 3;
    int unit = ((nn >> 5) << 3) + (nn & 7);
    int no   = gate * 256 + unit;
    float v;
    if (l == 0) v = bih0[no] + bhh0[no];
    else        v = bih[(size_t)(l - 1) * G4 + no] + bhh[(size_t)(l - 1) * G4 + no];
    g_bias[t] = v;
}

// round to tf32 + k-interleave, 8 floats per thread
__global__ void __launch_bounds__(256) round_ilv(const float* __restrict__ src,
                                                 float* __restrict__ dst) {
    size_t t = (size_t)blockIdx.x * blockDim.x + threadIdx.x;   // 8-float group idx
    const float* s = src + t * 8;
    float4 v0 = *(const float4*)s;
    float4 v1 = *(const float4*)(s + 4);
    ilv_store8(v0, v1, dst + t * 8);
}

// ---------------- launch ----------------
extern "C" void kernel_launch(void* const* d_in, const int* in_sizes, int n_in,
                              void* d_out, int out_size)
{
    const float* x     = (const float*)d_in[0];
    const float* h_all = (const float*)d_in[1];
    const float* c_all = (const float*)d_in[2];
    const float* Wih0  = (const float*)d_in[3];
    const float* Whh0  = (const float*)d_in[4];
    const float* bih0  = (const float*)d_in[5];
    const float* bhh0  = (const float*)d_in[6];
    const float* Wih   = (const float*)d_in[7];
    const float* Whh   = (const float*)d_in[8];
    const float* bih   = (const float*)d_in[9];
    const float* bhh   = (const float*)d_in[10];
    const float* Wout  = (const float*)d_in[11];
    const float* bout  = (const float*)d_in[12];

    float* out = (float*)d_out;
    float* hs  = out + (size_t)BB * OUTF;
    float* cs  = hs + (size_t)(LL + 1) * BB * HH;

    float *w, *wout, *biasc, *xtf, *halltf, *htf;
    cudaGetSymbolAddress((void**)&w,      g_w);
    cudaGetSymbolAddress((void**)&wout,   g_wout);
    cudaGetSymbolAddress((void**)&biasc,  g_bias);
    cudaGetSymbolAddress((void**)&xtf,    g_x_tf);
    cudaGetSymbolAddress((void**)&halltf, g_hall_tf);
    cudaGetSymbolAddress((void**)&htf,    g_h_tf);

    cudaFuncSetAttribute(mma_gemm<true>,  cudaFuncAttributeMaxDynamicSharedMemorySize, SMEMSZ);
    cudaFuncSetAttribute(mma_gemm<false>, cudaFuncAttributeMaxDynamicSharedMemorySize, SMEMSZ);

    conv_w<<<2048, 256>>>(Wih0, Whh0, Wih, Whh);
    conv_wout<<<32, 256>>>(Wout);
    conv_bias<<<32, 256>>>(bih0, bhh0, bih, bhh);
    round_ilv<<<(BB * HH / 8) / 256, 256>>>(x, xtf);
    round_ilv<<<((size_t)(LL + 1) * BB * HH / 8) / 256, 256>>>(h_all, halltf);

    for (int l = 0; l <= LL; ++l) {
        const float* a1 = (l == 0) ? xtf : htf;
        mma_gemm<true><<<dim3(G4 / TN, BB / TM), NTHREADS, SMEMSZ>>>(
            a1, halltf + (size_t)l * BB * HH,
            w + (size_t)l * G4 * KT, KT, KT,
            biasc + (size_t)l * G4,
            nullptr, 0,
            c_all + (size_t)l * BB * HH,
            hs + (size_t)l * BB * HH, cs + (size_t)l * BB * HH,
            htf);
    }

    // output = h_last @ Wout.T + bout
    mma_gemm<false><<<dim3(OUTF / TN, BB / TM), NTHREADS, SMEMSZ>>>(
        htf, nullptr,
        wout, HH, HH,
        bout, out, OUTF,
        nullptr, nullptr, nullptr, nullptr);
}

// round 16
// speedup vs baseline: 1.2082x; 1.2082x over previous
#include <cuda_runtime.h>
#include <stdint.h>
#include <math.h>

#define BB   16384
#define HH   256
#define OUTF 256
#define LL   7
#define G4   1024
#define KT   512

// ---------------- scratch (__device__ globals; no allocs allowed) ----------------
__device__ __align__(256) float g_w[(size_t)(LL + 1) * G4 * KT];   // tf32-rounded, gate-reordered, [Wih|Whh] K-concat
__device__ __align__(256) float g_wout[OUTF * HH];                 // tf32-rounded
__device__ __align__(256) float g_bias[(LL + 1) * G4];             // combined (bi+bh), gate-reordered
__device__ __align__(256) float g_x_tf[(size_t)BB * HH];           // tf32-rounded x
__device__ __align__(256) float g_hall_tf[(size_t)(LL + 1) * BB * HH]; // tf32-rounded h_all (slab0 by prep; slabs 1.. by epilogues)
__device__ __align__(256) float g_h_tf[2][(size_t)BB * HH];        // tf32-rounded h, PING-PONG (layer l writes [l&1], reads [(l-1)&1])

// ---------------- PTX helpers (arch-portable, sm_80+ baseline) ----------------
__device__ __forceinline__ uint32_t smem_u32(const void* p) {
    uint32_t a;
    asm("{ .reg .u64 t; cvta.to.shared.u64 t, %1; cvt.u32.u64 %0, t; }" : "=r"(a) : "l"(p));
    return a;
}
__device__ __forceinline__ void cp16(uint32_t s, const void* g) {
    asm volatile("cp.async.cg.shared.global [%0], [%1], 16;" :: "r"(s), "l"(g));
}
__device__ __forceinline__ uint32_t lds_u32(uint32_t addr) {
    uint32_t u; asm volatile("ld.shared.b32 %0, [%1];" : "=r"(u) : "r"(addr));
    return u;
}
__device__ __forceinline__ void mma1688(float c[4], const uint32_t a[4],
                                        uint32_t b0, uint32_t b1) {
    asm volatile("mma.sync.aligned.m16n8k8.row.col.f32.tf32.tf32.f32 "
        "{%0,%1,%2,%3}, {%4,%5,%6,%7}, {%8,%9}, {%0,%1,%2,%3};"
        : "+f"(c[0]), "+f"(c[1]), "+f"(c[2]), "+f"(c[3])
        : "r"(a[0]), "r"(a[1]), "r"(a[2]), "r"(a[3]), "r"(b0), "r"(b1));
}
__device__ __forceinline__ float rna_tf32(float x) {
    uint32_t u; asm("cvt.rna.tf32.f32 %0, %1;" : "=r"(u) : "f"(x));
    return __uint_as_float(u);
}
__device__ __forceinline__ float sigf(float x) {
    return __fdividef(1.0f, 1.0f + __expf(-x));
}
__device__ __forceinline__ float tanhfast(float x) {
    return __fdividef(2.0f, 1.0f + __expf(-2.0f * x)) - 1.0f;
}

// ---------------- tf32 TN GEMM via mma.sync, 3-stage cp.async, fused LSTM epilogue ----------------
#define TM 128
#define TN 128
#define NTHREADS 256
#define ROWB 144                           // 128B data + 16B pad
#define STAGE_A (TM * ROWB)                // 18 KB
#define STAGE_B (TN * ROWB)                // 18 KB
#define STAGE   (STAGE_A + STAGE_B)        // 36 KB
#define NSTAGE  3
#define SMEMSZ  (NSTAGE * STAGE)           // 108 KB -> 2 CTAs/SM

template<bool FUSED>
__global__ void __launch_bounds__(NTHREADS, 2) mma_gemm(
    const float* __restrict__ A1, const float* __restrict__ A2,
    const float* __restrict__ B, int sB, int Ktot,
    const float* __restrict__ bias,
    float* __restrict__ C, int sC,
    const float* __restrict__ c_in, float* __restrict__ h_out, float* __restrict__ c_out,
    float* __restrict__ htf_out,
    const float* __restrict__ hall_next, float* __restrict__ halltf_next)
{
    extern __shared__ __align__(128) char dsm[];
    const int tid  = threadIdx.x;
    const int lane = tid & 31;
    const int wid  = tid >> 5;
    const int wm   = wid & 1;        // 2 warps along M (64 rows)
    const int wn   = wid >> 1;       // 4 warps along N (32 cols)
    const int m0   = blockIdx.y * TM;
    const int n0   = blockIdx.x * TN;
    const uint32_t sbase = smem_u32(dsm);

    const int niter = Ktot >> 5;     // BK = 32

    float c[4][4][4];
    #pragma unroll
    for (int i = 0; i < 4; ++i)
        #pragma unroll
        for (int j = 0; j < 4; ++j)
            #pragma unroll
            for (int q = 0; q < 4; ++q) c[i][j][q] = 0.0f;

    auto load_stage = [&](int buf, int it) {
        const int kc = it << 5;
        const uint32_t sa = sbase + buf * STAGE;
        const uint32_t sb = sa + STAGE_A;
        const float* Asrc; int koff;
        if (kc < 256) { Asrc = A1; koff = kc; } else { Asrc = A2; koff = kc - 256; }
        #pragma unroll
        for (int i = 0; i < 4; ++i) {                    // A: 128 rows x 8 chunks of 16B
            int idx = tid + i * NTHREADS;
            int row = idx >> 3, kg = idx & 7;
            cp16(sa + row * ROWB + (kg << 4),
                 Asrc + (size_t)(m0 + row) * 256 + koff + kg * 4);
        }
        #pragma unroll
        for (int i = 0; i < 4; ++i) {                    // B: 128 rows x 8 chunks
            int idx = tid + i * NTHREADS;
            int row = idx >> 3, kg = idx & 7;
            cp16(sb + row * ROWB + (kg << 4),
                 B + (size_t)(n0 + row) * sB + kc + kg * 4);
        }
        asm volatile("cp.async.commit_group;");
    };

    load_stage(0, 0);
    load_stage(1, 1);

    const int lr = lane >> 2;   // 0..7
    const int lc = lane & 3;    // k-low

    int buf = 0;
    #pragma unroll 1
    for (int i = 0; i < niter; ++i) {
        // stage i ready when at most 1 newer group pending (groups retire in order)
        if (i == niter - 1) asm volatile("cp.async.wait_group 0;");
        else                asm volatile("cp.async.wait_group 1;");
        // single sync: also retires buffer (i+2)%3 (last computed at iter i-1)
        __syncthreads();
        if (i + 2 < niter) load_stage((buf + 2) % NSTAGE, i + 2);

        const uint32_t sa = sbase + buf * STAGE;
        const uint32_t sb = sa + STAGE_A;
        const uint32_t abase = sa + (wm * 64 + lr) * ROWB + lc * 4;
        const uint32_t bbase = sb + (wn * 32 + lr) * ROWB + lc * 4;

        #pragma unroll
        for (int ks = 0; ks < 4; ++ks) {                 // 4 k8 steps per BK=32
            const int o0 = ks * 32;                      // ch0 byte offset
            const int o1 = o0 + 16;                      // ch1
            uint32_t a[4][4];
            #pragma unroll
            for (int mi = 0; mi < 4; ++mi) {
                const uint32_t ab = abase + mi * (16 * ROWB);
                a[mi][0] = lds_u32(ab + o0);
                a[mi][1] = lds_u32(ab + 8 * ROWB + o0);
                a[mi][2] = lds_u32(ab + o1);
                a[mi][3] = lds_u32(ab + 8 * ROWB + o1);
            }
            uint32_t b[4][2];
            #pragma unroll
            for (int nj = 0; nj < 4; ++nj) {
                const uint32_t bb = bbase + nj * (8 * ROWB);
                b[nj][0] = lds_u32(bb + o0);
                b[nj][1] = lds_u32(bb + o1);
            }
            #pragma unroll
            for (int mi = 0; mi < 4; ++mi)
                #pragma unroll
                for (int nj = 0; nj < 4; ++nj)
                    mma1688(c[mi][nj], a[mi], b[nj][0], b[nj][1]);
        }
        buf = (buf + 1 == NSTAGE) ? 0 : buf + 1;
    }

    if (!FUSED) {
        #pragma unroll
        for (int mi = 0; mi < 4; ++mi) {
            const int r0 = m0 + wm * 64 + mi * 16 + lr;
            #pragma unroll
            for (int nj = 0; nj < 4; ++nj) {
                const int col = n0 + wn * 32 + nj * 8 + lc * 2;
                float bx = 0.0f, by = 0.0f;
                if (bias) { bx = bias[col]; by = bias[col + 1]; }
                *(float2*)&C[(size_t)r0 * sC + col] =
                    make_float2(c[mi][nj][0] + bx, c[mi][nj][1] + by);
                *(float2*)&C[(size_t)(r0 + 8) * sC + col] =
                    make_float2(c[mi][nj][2] + bx, c[mi][nj][3] + by);
            }
        }
    } else {
        // fused LSTM epilogue (gate-reordered cols: thread's 4 nj = gates i,f,g,o of
        // units ub, ub+1). Writes h/c fp32 outputs, tf32 h into the PING-PONG buffer
        // (never the one this launch reads), and pre-rounds the next h_all slab.
        const int ub = ((n0 + wn * 32) >> 2) + (lc << 1);
        float bsv[4][2];
        #pragma unroll
        for (int g = 0; g < 4; ++g) {
            bsv[g][0] = bias[n0 + wn * 32 + g * 8 + lc * 2];
            bsv[g][1] = bias[n0 + wn * 32 + g * 8 + lc * 2 + 1];
        }
        #pragma unroll
        for (int mi = 0; mi < 4; ++mi) {
            #pragma unroll
            for (int rh = 0; rh < 2; ++rh) {
                const int row = m0 + wm * 64 + mi * 16 + rh * 8 + lr;
                const float2 cin = *(const float2*)&c_in[(size_t)row * HH + ub];
                float hv[2], cv[2];
                #pragma unroll
                for (int e = 0; e < 2; ++e) {
                    const int q = rh * 2 + e;
                    float gi = sigf    (c[mi][0][q] + bsv[0][e]);
                    float gf = sigf    (c[mi][1][q] + bsv[1][e]);
                    float gg = tanhfast(c[mi][2][q] + bsv[2][e]);
                    float go = sigf    (c[mi][3][q] + bsv[3][e]);
                    float ci = e ? cin.y : cin.x;
                    cv[e] = gf * ci + gi * gg;
                    hv[e] = go * tanhfast(cv[e]);
                }
                *(float2*)&c_out[(size_t)row * HH + ub] = make_float2(cv[0], cv[1]);
                *(float2*)&h_out[(size_t)row * HH + ub] = make_float2(hv[0], hv[1]);
                *(float2*)&htf_out[(size_t)row * HH + ub] =
                    make_float2(rna_tf32(hv[0]), rna_tf32(hv[1]));
                if (hall_next) {
                    const float2 hn = *(const float2*)&hall_next[(size_t)row * HH + ub];
                    *(float2*)&halltf_next[(size_t)row * HH + ub] =
                        make_float2(rna_tf32(hn.x), rna_tf32(hn.y));
                }
            }
        }
    }
}

// ---------------- repack / rounding kernels (once per call) ----------------
__global__ void __launch_bounds__(256) conv_w(
    const float* __restrict__ Wih0, const float* __restrict__ Whh0,
    const float* __restrict__ Wih,  const float* __restrict__ Whh)
{
    int t  = blockIdx.x * blockDim.x + threadIdx.x;     // 1048576
    int k4 = (t & 127) << 2;
    int nn = (t >> 7) & 1023;
    int l  = t >> 17;
    int gate = (nn >> 3) & 3;
    int unit = ((nn >> 5) << 3) + (nn & 7);
    int no   = gate * 256 + unit;
    const float* src;
    if (l == 0) src = (k4 < 256) ? (Wih0 + (size_t)no * 256 + k4)
                                 : (Whh0 + (size_t)no * 256 + (k4 - 256));
    else        src = (k4 < 256) ? (Wih + ((size_t)(l - 1) * G4 + no) * 256 + k4)
                                 : (Whh + ((size_t)(l - 1) * G4 + no) * 256 + (k4 - 256));
    float4 v = *(const float4*)src;
    v.x = rna_tf32(v.x); v.y = rna_tf32(v.y); v.z = rna_tf32(v.z); v.w = rna_tf32(v.w);
    *(float4*)&g_w[((size_t)l * G4 + nn) * KT + k4] = v;
}

__global__ void __launch_bounds__(256) conv_wout(const float* __restrict__ Wout) {
    int t = blockIdx.x * blockDim.x + threadIdx.x;      // 16384
    int n = t >> 6, k4 = (t & 63) << 2;
    float4 v = *(const float4*)(Wout + (size_t)n * HH + k4);
    v.x = rna_tf32(v.x); v.y = rna_tf32(v.y); v.z = rna_tf32(v.z); v.w = rna_tf32(v.w);
    *(float4*)&g_wout[(size_t)n * HH + k4] = v;
}

__global__ void __launch_bounds__(256) conv_bias(
    const float* __restrict__ bih0, const float* __restrict__ bhh0,
    const float* __restrict__ bih,  const float* __restrict__ bhh)
{
    int t  = blockIdx.x * blockDim.x + threadIdx.x;     // 8192
    int nn = t & 1023;
    int l  = t >> 10;
    int gate = (nn >> 3) & 3;
    int unit = ((nn >> 5) << 3) + (nn & 7);
    int no   = gate * 256 + unit;
    float v;
    if (l == 0) v = bih0[no] + bhh0[no];
    else        v = bih[(size_t)(l - 1) * G4 + no] + bhh[(size_t)(l - 1) * G4 + no];
    g_bias[t] = v;
}

// round a slab to tf32 (x and h_all[0] only; later slabs handled by GEMM epilogues)
__global__ void __launch_bounds__(256) round_tf(const float* __restrict__ src,
                                                float* __restrict__ dst) {
    size_t t = (size_t)blockIdx.x * blockDim.x + threadIdx.x;   // float4 index
    float4 v = *(const float4*)(src + t * 4);
    v.x = rna_tf32(v.x); v.y = rna_tf32(v.y); v.z = rna_tf32(v.z); v.w = rna_tf32(v.w);
    *(float4*)(dst + t * 4) = v;
}

// ---------------- launch ----------------
extern "C" void kernel_launch(void* const* d_in, const int* in_sizes, int n_in,
                              void* d_out, int out_size)
{
    const float* x     = (const float*)d_in[0];
    const float* h_all = (const float*)d_in[1];
    const float* c_all = (const float*)d_in[2];
    const float* Wih0  = (const float*)d_in[3];
    const float* Whh0  = (const float*)d_in[4];
    const float* bih0  = (const float*)d_in[5];
    const float* bhh0  = (const float*)d_in[6];
    const float* Wih   = (const float*)d_in[7];
    const float* Whh   = (const float*)d_in[8];
    const float* bih   = (const float*)d_in[9];
    const float* bhh   = (const float*)d_in[10];
    const float* Wout  = (const float*)d_in[11];
    const float* bout  = (const float*)d_in[12];

    float* out = (float*)d_out;
    float* hs  = out + (size_t)BB * OUTF;
    float* cs  = hs + (size_t)(LL + 1) * BB * HH;

    float *w, *wout, *biasc, *xtf, *halltf, *htf0;
    cudaGetSymbolAddress((void**)&w,      g_w);
    cudaGetSymbolAddress((void**)&wout,   g_wout);
    cudaGetSymbolAddress((void**)&biasc,  g_bias);
    cudaGetSymbolAddress((void**)&xtf,    g_x_tf);
    cudaGetSymbolAddress((void**)&halltf, g_hall_tf);
    cudaGetSymbolAddress((void**)&htf0,   g_h_tf);
    float* htfb[2] = { htf0, htf0 + (size_t)BB * HH };

    cudaFuncSetAttribute(mma_gemm<true>,  cudaFuncAttributeMaxDynamicSharedMemorySize, SMEMSZ);
    cudaFuncSetAttribute(mma_gemm<false>, cudaFuncAttributeMaxDynamicSharedMemorySize, SMEMSZ);

    conv_w<<<4096, 256>>>(Wih0, Whh0, Wih, Whh);
    conv_wout<<<64, 256>>>(Wout);
    conv_bias<<<32, 256>>>(bih0, bhh0, bih, bhh);
    round_tf<<<(BB * HH / 4) / 256, 256>>>(x, xtf);
    round_tf<<<(BB * HH / 4) / 256, 256>>>(h_all, halltf);   // slab 0 only

    for (int l = 0; l <= LL; ++l) {
        const float* a1 = (l == 0) ? xtf : htfb[(l - 1) & 1];   // read previous ping-pong slab
        const float* hnext   = (l < LL) ? h_all + (size_t)(l + 1) * BB * HH : nullptr;
        float*       hnexttf = (l < LL) ? halltf + (size_t)(l + 1) * BB * HH : nullptr;
        mma_gemm<true><<<dim3(G4 / TN, BB / TM), NTHREADS, SMEMSZ>>>(
            a1, halltf + (size_t)l * BB * HH,
            w + (size_t)l * G4 * KT, KT, KT,
            biasc + (size_t)l * G4,
            nullptr, 0,
            c_all + (size_t)l * BB * HH,
            hs + (size_t)l * BB * HH, cs + (size_t)l * BB * HH,
            htfb[l & 1],                                         // write current slab (never read this launch)
            hnext, hnexttf);
    }

    // output = h_last @ Wout.T + bout  (reads layer-7 slab: htfb[LL & 1])
    mma_gemm<false><<<dim3(OUTF / TN, BB / TM), NTHREADS, SMEMSZ>>>(
        htfb[LL & 1], nullptr,
        wout, HH, HH,
        bout, out, OUTF,
        nullptr, nullptr, nullptr, nullptr, nullptr, nullptr);
}